// round 4
// baseline (speedup 1.0000x reference)
#include <cuda_runtime.h>
#include <cstdint>

// Problem constants
#define BB   32
#define KK_  3
#define NN   512
#define FIN  64
#define FOUT 64
#define TT   64
// Derived
#define KC   (KK_ * NN)          // 1536 contraction depth
#define CC   (FOUT * TT)         // 4096 output cols per row

// Scratch (allocation-free rule: __device__ globals)
__device__ float g_aeff[(size_t)BB * NN * KC];          // [b][n][k*512+m]  ~100.7 MB
__device__ float g_xt  [(size_t)BB * KC * CC];          // [b][k*512+m][o*64+t] ~805 MB

typedef unsigned long long u64;

__device__ __forceinline__ u64 pk2(float x, float y) {
    u64 r; asm("mov.b64 %0, {%1, %2};" : "=l"(r) : "f"(x), "f"(y)); return r;
}
__device__ __forceinline__ void fma2(u64 &c, u64 a, u64 b) {
    asm("fma.rn.f32x2 %0, %1, %2, %0;" : "+l"(c) : "l"(a), "l"(b));
}
__device__ __forceinline__ void unpk2(u64 v, float &x, float &y) {
    asm("mov.b64 {%0, %1}, %2;" : "=f"(x), "=f"(y) : "l"(v));
}

// ---------------------------------------------------------------------------
// K1: combined = scores + adj*mask; softmax over last axis; A_eff = cheb * sm
// Writes A_eff transposed to [b][n][k*512+m] so K3 sees a plain [512,1536] A.
// grid (N, K, B), block 128; each thread owns one float4 (4 of 512 elems).
// ---------------------------------------------------------------------------
__global__ __launch_bounds__(128)
void k_aeff(const float* __restrict__ sc, const float* __restrict__ adj,
            const float* __restrict__ mask, const float* __restrict__ cheb)
{
    int n = blockIdx.x, k = blockIdx.y, b = blockIdx.z;
    const float4* s4 = (const float4*)(sc   + (((size_t)(b * KK_ + k)) * NN + n) * NN);
    const float4* a4 = (const float4*)(adj  + (size_t)n * NN);
    const float4* m4 = (const float4*)(mask + ((size_t)(k * NN + n)) * NN);
    const float4* c4 = (const float4*)(cheb + ((size_t)(k * NN + n)) * NN);
    float4*       o4 = (float4*)(g_aeff + ((size_t)(b * NN + n)) * KC + k * NN);

    int t = threadIdx.x;
    float4 sv = s4[t], av = a4[t], mv = m4[t];
    float v0 = sv.x + av.x * mv.x;
    float v1 = sv.y + av.y * mv.y;
    float v2 = sv.z + av.z * mv.z;
    float v3 = sv.w + av.w * mv.w;

    float mx = fmaxf(fmaxf(v0, v1), fmaxf(v2, v3));
    __shared__ float red[4];
    #pragma unroll
    for (int o = 16; o; o >>= 1) mx = fmaxf(mx, __shfl_xor_sync(0xffffffffu, mx, o));
    if ((t & 31) == 0) red[t >> 5] = mx;
    __syncthreads();
    mx = fmaxf(fmaxf(red[0], red[1]), fmaxf(red[2], red[3]));
    __syncthreads();

    v0 = __expf(v0 - mx); v1 = __expf(v1 - mx);
    v2 = __expf(v2 - mx); v3 = __expf(v3 - mx);
    float s = v0 + v1 + v2 + v3;
    #pragma unroll
    for (int o = 16; o; o >>= 1) s += __shfl_xor_sync(0xffffffffu, s, o);
    if ((t & 31) == 0) red[t >> 5] = s;
    __syncthreads();
    s = red[0] + red[1] + red[2] + red[3];
    float inv = 1.0f / s;

    float4 cv = c4[t];
    float4 ov;
    ov.x = cv.x * v0 * inv; ov.y = cv.y * v1 * inv;
    ov.z = cv.z * v2 * inv; ov.w = cv.w * v3 * inv;
    o4[t] = ov;
}

// ---------------------------------------------------------------------------
// K2: XT[b,k,m,o,t] = sum_i x[b,m,i,t] * Theta[k,i,o]
// grid (N, B), block 256. Per CTA: X = x[b,m] (64x64) in smem, loop k over 3
// Theta matrices. 4x4 micro per thread, packed f32x2 FMAs.
// ---------------------------------------------------------------------------
__global__ __launch_bounds__(256)
void k_xtheta(const float* __restrict__ x, const float* __restrict__ Theta)
{
    int m = blockIdx.x, b = blockIdx.y;
    __shared__ float Xs[FIN * TT];   // [i][t]
    __shared__ float Ts[FIN * FOUT]; // [i][o]

    int tid = threadIdx.x;
    const float4* xb4 = (const float4*)(x + ((size_t)(b * NN + m)) * (FIN * TT));
    float4* Xs4 = (float4*)Xs;
    #pragma unroll
    for (int r = 0; r < 4; r++) Xs4[tid + r * 256] = xb4[tid + r * 256];

    int tx = tid & 15;   // t-quad
    int ty = tid >> 4;   // o-quad

    for (int k = 0; k < KK_; k++) {
        __syncthreads();  // Xs ready (k=0) / previous compute done (k>0)
        const float4* th4 = (const float4*)(Theta + (size_t)k * FIN * FOUT);
        float4* Ts4 = (float4*)Ts;
        #pragma unroll
        for (int r = 0; r < 4; r++) Ts4[tid + r * 256] = th4[tid + r * 256];
        __syncthreads();

        u64 acc[4][2] = {};
        #pragma unroll 8
        for (int i = 0; i < FIN; i++) {
            float4 th = ((const float4*)(Ts + i * FOUT))[ty];
            float4 xv = ((const float4*)(Xs + i * TT))[tx];
            u64 b01 = pk2(xv.x, xv.y), b23 = pk2(xv.z, xv.w);
            u64 a0 = pk2(th.x, th.x), a1 = pk2(th.y, th.y);
            u64 a2 = pk2(th.z, th.z), a3 = pk2(th.w, th.w);
            fma2(acc[0][0], a0, b01); fma2(acc[0][1], a0, b23);
            fma2(acc[1][0], a1, b01); fma2(acc[1][1], a1, b23);
            fma2(acc[2][0], a2, b01); fma2(acc[2][1], a2, b23);
            fma2(acc[3][0], a3, b01); fma2(acc[3][1], a3, b23);
        }

        float* orow = g_xt + ((size_t)((b * KK_ + k) * NN + m)) * CC;
        #pragma unroll
        for (int oi = 0; oi < 4; oi++) {
            float4 v;
            unpk2(acc[oi][0], v.x, v.y);
            unpk2(acc[oi][1], v.z, v.w);
            *(float4*)(orow + (size_t)(ty * 4 + oi) * TT + tx * 4) = v;
        }
    }
}

// ---------------------------------------------------------------------------
// K3: per-b GEMM + ReLU: out[b] (512x4096) = A_eff[b] (512x1536) @ XT[b] (1536x4096)
// CTA tile 128x64, BK=32, 256 threads, 8x4 micro per thread, f32x2 FMAs.
// grid (4096/64, 512/128, B) = (64, 4, 32).
// ---------------------------------------------------------------------------
__global__ __launch_bounds__(256)
void k_gemm_relu(float* __restrict__ Cg)
{
    const int BM = 128, BN = 64, BK = 32;
    int ct = blockIdx.x, nt = blockIdx.y, b = blockIdx.z;

    const float* A  = g_aeff + ((size_t)b * NN + nt * BM) * KC;
    const float* Bm = g_xt   + (size_t)b * KC * CC + ct * BN;
    float*       C  = Cg     + ((size_t)b * NN + nt * BM) * CC + ct * BN;

    __shared__ float As[BM * BK];   // [row][kk], 16 KB
    __shared__ float Bs[BK * BN];   // [kk][c],   8 KB

    int tid = threadIdx.x;
    int tx = tid & 15;   // c-quad
    int ty = tid >> 4;   // n-octet

    u64 acc[8][2] = {};

    for (int kt = 0; kt < KC / BK; kt++) {
        __syncthreads();
        // A tile: 128 rows x 32 cols = 1024 float4, 4 per thread (coalesced)
        #pragma unroll
        for (int r = 0; r < 4; r++) {
            int lin = tid + r * 256;
            int row = lin >> 3, q = lin & 7;
            float4 v = *(const float4*)(A + (size_t)row * KC + kt * BK + q * 4);
            *(float4*)(As + row * BK + q * 4) = v;
        }
        // B tile: 32 rows x 64 cols = 512 float4, 2 per thread (coalesced)
        #pragma unroll
        for (int r = 0; r < 2; r++) {
            int lin = tid + r * 256;
            int row = lin >> 4, q = lin & 15;
            float4 v = *(const float4*)(Bm + (size_t)(kt * BK + row) * CC + q * 4);
            *(float4*)(Bs + row * BN + q * 4) = v;
        }
        __syncthreads();

        #pragma unroll 8
        for (int kk = 0; kk < BK; kk++) {
            float4 bv = ((const float4*)(Bs + kk * BN))[tx];
            u64 b01 = pk2(bv.x, bv.y), b23 = pk2(bv.z, bv.w);
            #pragma unroll
            for (int i = 0; i < 8; i++) {
                float a = As[(ty * 8 + i) * BK + kk];  // broadcast LDS
                u64 a2 = pk2(a, a);
                fma2(acc[i][0], a2, b01);
                fma2(acc[i][1], a2, b23);
            }
        }
    }

    #pragma unroll
    for (int i = 0; i < 8; i++) {
        float o0, o1, o2, o3;
        unpk2(acc[i][0], o0, o1);
        unpk2(acc[i][1], o2, o3);
        float4 v = make_float4(fmaxf(o0, 0.f), fmaxf(o1, 0.f),
                               fmaxf(o2, 0.f), fmaxf(o3, 0.f));
        *(float4*)(C + (size_t)(ty * 8 + i) * CC + tx * 4) = v;
    }
}

// ---------------------------------------------------------------------------
extern "C" void kernel_launch(void* const* d_in, const int* in_sizes, int n_in,
                              void* d_out, int out_size)
{
    const float* x     = (const float*)d_in[0];  // [B,N,F_IN,T]
    const float* sc    = (const float*)d_in[1];  // [B,K,N,N]
    const float* adj   = (const float*)d_in[2];  // [N,N]
    const float* cheb  = (const float*)d_in[3];  // [K,N,N]
    const float* Theta = (const float*)d_in[4];  // [K,F_IN,F_OUT]
    const float* mask  = (const float*)d_in[5];  // [K,N,N]
    float* out = (float*)d_out;                  // [B,N,F_OUT,T]
    (void)in_sizes; (void)n_in; (void)out_size;

    k_aeff<<<dim3(NN, KK_, BB), 128>>>(sc, adj, mask, cheb);
    k_xtheta<<<dim3(NN, BB), 256>>>(x, Theta);
    k_gemm_relu<<<dim3(CC / 64, NN / 128, BB), 256>>>(out);
}